// round 15
// baseline (speedup 1.0000x reference)
#include <cuda_runtime.h>
#include <cstdint>

#define H 512
#define W 512
#define NIMG 48
#define TRB 16                  // output rows per block band
#define BLOCK 256
#define RD 16                   // smem ring depth (rows)

__device__ __forceinline__ float med3f(float a, float b, float c) {
    return fmaxf(fminf(a, b), fminf(fmaxf(a, b), c));
}

__device__ __forceinline__ void cp16(uint32_t daddr, const float* g) {
    asm volatile("cp.async.ca.shared.global [%0], [%1], 16;" :: "r"(daddr), "l"(g) : "memory");
}
__device__ __forceinline__ void cp_commit() {
    asm volatile("cp.async.commit_group;" ::: "memory");
}
template <int N> __device__ __forceinline__ void cp_wait() {
    asm volatile("cp.async.wait_group %0;" :: "n"(N) : "memory");
}

__global__ __launch_bounds__(BLOCK)
void MedianFilter_22737556865485_kernel(const float* __restrict__ in,
                                        float* __restrict__ out) {
    // 4-word guards front/back so the (SEL-discarded) edge LDS at word -1 / +8192 stays in-bounds.
    __shared__ float smem[4 + RD * W + 4];
    float* const ring = smem + 4;

    const int t    = threadIdx.x;
    const int r0   = blockIdx.x * TRB;
    const int img  = blockIdx.y;
    const bool t0  = (t == 0), t255 = (t == BLOCK - 1);

    const float* base  = in  + (size_t)img * (H * W);
    float*       obase = out + (size_t)img * (H * W);

    const uint32_t sb = (uint32_t)__cvta_generic_to_shared(ring);
    const int rr4 = t >> 6;         // which of 4 rows this thread fills (fill4)
    const int kk4 = t & 63;         // 16B chunk within the row (x2)
    const int rr2 = t >> 7;         // which of 2 rows (fill2)
    const int kk2 = t & 127;        // 16B chunk within the row (x1)

    // gmem row pointer for ring index j (row r0-1+j), reflected at both image edges.
    auto gRow = [&](int j) -> const float* {
        int g = r0 - 1 + j;
        g = (g < 0) ? 1 : g;
        g = (g >= H) ? (2 * H - 2 - g) : g;
        return base + (size_t)g * W;
    };
    // Fill rows j..j+3 as ONE commit group: 256 threads x 2 x 16B, fully coalesced.
    auto fill4 = [&](int j) {
        const int jj = j + rr4;
        const int slot = jj & (RD - 1);
        const float* g = gRow(jj);
        cp16(sb + (uint32_t)((slot * W + kk4 * 4) * 4),        g + kk4 * 4);
        cp16(sb + (uint32_t)((slot * W + (kk4 + 64) * 4) * 4), g + (kk4 + 64) * 4);
        cp_commit();
    };
    // Fill rows j..j+1 as ONE commit group: 256 threads x 16B.
    auto fill2 = [&](int j) {
        const int jj = j + rr2;
        const int slot = jj & (RD - 1);
        cp16(sb + (uint32_t)((slot * W + kk2 * 4) * 4), gRow(jj) + kk2 * 4);
        cp_commit();
    };

    // Prologue: 4 groups in flight — G0:{0..3} G1:{4..7} G2:{8..11} G3:{12..15}.
    fill4(0);
    fill4(4);
    fill4(8);
    fill4(12);

    // Row-triple history: lo/mi/hi over 3 horizontal neighbors, per pixel column.
    // mid on the FMA pipe: mid = (a+b+c) - min3 - max3.
    float loA[3], miA[3], hiA[3];   // px col 2t
    float loB[3], miB[3], hiB[3];   // px col 2t+1

    auto triple = [&](int j) {      // j, j%3, j&(RD-1) compile-time under full unroll
        const float* rowp = ring + (j & (RD - 1)) * W;
        const float2 m = *reinterpret_cast<const float2*>(rowp + 2 * t);
        const float a = t0   ? m.y : rowp[2 * t - 1];   // reflect col -1 -> 1
        const float d = t255 ? m.x : rowp[2 * t + 2];   // reflect col W -> W-2
        const int h = j % 3;
        const float sA = (a + m.x) + m.y;               // FMA pipe
        const float sB = (m.x + m.y) + d;               // FMA pipe
        loA[h] = fminf(fminf(a, m.x), m.y);             // ALU pipe
        hiA[h] = fmaxf(fmaxf(a, m.x), m.y);
        miA[h] = (sA - loA[h]) - hiA[h];                // FMA pipe
        loB[h] = fminf(fminf(m.x, m.y), d);
        hiB[h] = fmaxf(fmaxf(m.x, m.y), d);
        miB[h] = (sB - loB[h]) - hiB[h];                // FMA pipe
    };
    auto combine = [&](float2* po) {
        const float A0 = fmaxf(fmaxf(loA[0], loA[1]), loA[2]);  // max of mins
        const float C0 = fminf(fminf(hiA[0], hiA[1]), hiA[2]);  // min of maxes
        const float B0 = med3f(miA[0], miA[1], miA[2]);         // med of mids
        const float A1 = fmaxf(fmaxf(loB[0], loB[1]), loB[2]);
        const float C1 = fminf(fminf(hiB[0], hiB[1]), hiB[2]);
        const float B1 = med3f(miB[0], miB[1], miB[2]);
        *po = make_float2(med3f(A0, B0, C0), med3f(A1, B1, C1));
    };

    // Prime history with rows j=0,1 (G0 complete after wait<3>).
    cp_wait<3>();
    __syncthreads();
    triple(0);
    triple(1);

    float* po = obase + (size_t)r0 * W + 2 * t;

    // 4 output rows per iteration: iter i consumes ring rows 4i+2 .. 4i+5.
    // The wrap-around fill (rows 16,17 -> slots 0,1) is issued AFTER iter 1's
    // barrier: every earlier read of slots 0,1 (prologue prime) is ordered
    // before it by two barriers, and it is consumed 2 iterations later (i=3).
#pragma unroll
    for (int i = 0; i < TRB / 4; ++i) {
        if (i == 0)      { cp_wait<2>(); }              // G0,G1 done (rows 2-5)
        else if (i == 1) { cp_wait<1>(); }              // G2 done (rows 6-9)
        else if (i == 2) { cp_wait<1>(); }              // G3 done (rows 10-13); G4 flying
        else             { cp_wait<0>(); }              // G4 done (rows 16,17)
        __syncthreads();
        if (i == 1) fill2(16);                          // G4: rows 16,17 -> slots 0,1

        triple(4 * i + 2); combine(reinterpret_cast<float2*>(po));          // row 4i
        triple(4 * i + 3); combine(reinterpret_cast<float2*>(po + W));      // row 4i+1
        triple(4 * i + 4); combine(reinterpret_cast<float2*>(po + 2 * W));  // row 4i+2
        triple(4 * i + 5); combine(reinterpret_cast<float2*>(po + 3 * W));  // row 4i+3
        po += 4 * W;
    }
}

extern "C" void kernel_launch(void* const* d_in, const int* in_sizes, int n_in,
                              void* d_out, int out_size) {
    const float* in  = (const float*)d_in[0];
    float*       out = (float*)d_out;
    dim3 grid(H / TRB, NIMG);       // (32, 48) = 1536 blocks
    MedianFilter_22737556865485_kernel<<<grid, BLOCK>>>(in, out);
}

// round 16
// speedup vs baseline: 1.0793x; 1.0793x over previous
#include <cuda_runtime.h>
#include <cstdint>

#define H 512
#define W 512
#define NIMG 48
#define TRB 32                  // output rows per block band
#define BLOCK 256
#define RD 8                    // smem ring depth (rows)

__device__ __forceinline__ float med3f(float a, float b, float c) {
    return fmaxf(fminf(a, b), fminf(fmaxf(a, b), c));
}

__device__ __forceinline__ void cp16(uint32_t daddr, const float* g) {
    asm volatile("cp.async.ca.shared.global [%0], [%1], 16;" :: "r"(daddr), "l"(g) : "memory");
}
__device__ __forceinline__ void cp_commit() {
    asm volatile("cp.async.commit_group;" ::: "memory");
}
template <int N> __device__ __forceinline__ void cp_wait() {
    asm volatile("cp.async.wait_group %0;" :: "n"(N) : "memory");
}

__global__ __launch_bounds__(BLOCK)
void MedianFilter_22737556865485_kernel(const float* __restrict__ in,
                                        float* __restrict__ out) {
    // 4-word guards front/back so the (SEL-discarded) edge LDS at word -1 / +4096 stays in-bounds.
    __shared__ float smem[4 + RD * W + 4];
    float* const ring = smem + 4;

    const int t    = threadIdx.x;
    const int r0   = blockIdx.x * TRB;
    const int img  = blockIdx.y;
    const bool t0  = (t == 0), t255 = (t == BLOCK - 1);

    const float* base  = in  + (size_t)img * (H * W);
    float*       obase = out + (size_t)img * (H * W);

    const uint32_t sb = (uint32_t)__cvta_generic_to_shared(ring);
    const int rr = t >> 7;          // which of the 2 rows this thread fills
    const int k  = t & 127;         // 16B chunk within the row

    // gmem row pointer for ring index j (row r0-1+j), reflected at both image edges.
    auto gRow = [&](int j) -> const float* {
        int g = r0 - 1 + j;
        g = (g < 0) ? 1 : g;
        g = (g >= H) ? (2 * H - 2 - g) : g;
        return base + (size_t)g * W;
    };
    // Fill rows (j, j+1) as one commit group: 256 threads x 16B, fully coalesced.
    auto fill2 = [&](int j) {
        const int jj = j + rr;
        cp16(sb + (uint32_t)(((jj & (RD - 1)) * W + k * 4) * 4), gRow(jj) + k * 4);
        cp_commit();
    };

    // Paced prologue: 3 groups in flight — rows 0..5 (G0:{0,1} G1:{2,3} G2:{4,5}).
    fill2(0);
    fill2(2);
    fill2(4);

    // Row-triple history: lo/mi/hi over 3 horizontal neighbors, per pixel column.
    // mid on the FMA pipe: mid = (a+b+c) - min3 - max3.
    float loA[3], miA[3], hiA[3];   // px col 2t
    float loB[3], miB[3], hiB[3];   // px col 2t+1

    auto triple = [&](int j) {      // j, j%3, j&(RD-1) compile-time under full unroll
        const float* rowp = ring + (j & (RD - 1)) * W;
        const float2 m = *reinterpret_cast<const float2*>(rowp + 2 * t);
        const float a = t0   ? m.y : rowp[2 * t - 1];   // reflect col -1 -> 1
        const float d = t255 ? m.x : rowp[2 * t + 2];   // reflect col W -> W-2
        const int h = j % 3;
        const float sA = (a + m.x) + m.y;               // FMA pipe
        const float sB = (m.x + m.y) + d;               // FMA pipe
        loA[h] = fminf(fminf(a, m.x), m.y);             // ALU pipe
        hiA[h] = fmaxf(fmaxf(a, m.x), m.y);
        miA[h] = (sA - loA[h]) - hiA[h];                // FMA pipe
        loB[h] = fminf(fminf(m.x, m.y), d);
        hiB[h] = fmaxf(fmaxf(m.x, m.y), d);
        miB[h] = (sB - loB[h]) - hiB[h];                // FMA pipe
    };
    auto combine = [&](float2* po) {
        const float A0 = fmaxf(fmaxf(loA[0], loA[1]), loA[2]);  // max of mins
        const float C0 = fminf(fminf(hiA[0], hiA[1]), hiA[2]);  // min of maxes
        const float B0 = med3f(miA[0], miA[1], miA[2]);         // med of mids
        const float A1 = fmaxf(fmaxf(loB[0], loB[1]), loB[2]);
        const float C1 = fminf(fminf(hiB[0], hiB[1]), hiB[2]);
        const float B1 = med3f(miB[0], miB[1], miB[2]);
        *po = make_float2(med3f(A0, B0, C0), med3f(A1, B1, C1));
    };

    // Prime history with rows j=0,1 (G0 complete after wait<2>).
    cp_wait<2>();
    __syncthreads();
    triple(0);
    triple(1);

    float* po = obase + (size_t)r0 * W + 2 * t;

    // Steady state (identical pacing to the 19.8us kernel): iter i fills rows
    // {2i+6, 2i+7}, waits for group i+1 (rows {2i+2, 2i+3}) — 2 iterations of
    // cover. Ring write slots (2i+6,2i+7)%8 vs read slots (2i+2,2i+3)%8 are
    // disjoint; reuse of a slot is separated by two barriers.
#pragma unroll
    for (int i = 0; i < TRB / 2; ++i) {
        if (i < TRB / 2 - 2) {
            fill2(2 * i + 6);       // last fill at i=13: rows {32,33} (=TRB+1)
            cp_wait<2>();
        } else if (i == TRB / 2 - 2) {
            cp_wait<1>();
        } else {
            cp_wait<0>();
        }
        __syncthreads();

        triple(2 * i + 2);          // row r0+2i+1
        combine(reinterpret_cast<float2*>(po));          // output row r0+2i
        triple(2 * i + 3);          // row r0+2i+2
        combine(reinterpret_cast<float2*>(po + W));      // output row r0+2i+1
        po += 2 * W;
    }
}

extern "C" void kernel_launch(void* const* d_in, const int* in_sizes, int n_in,
                              void* d_out, int out_size) {
    const float* in  = (const float*)d_in[0];
    float*       out = (float*)d_out;
    dim3 grid(H / TRB, NIMG);       // (16, 48) = 768 blocks
    MedianFilter_22737556865485_kernel<<<grid, BLOCK>>>(in, out);
}